// round 16
// baseline (speedup 1.0000x reference)
#include <cuda_runtime.h>
#include <cstdint>

// ---------------- problem constants ----------------
#define En   1024
#define Hn   16
#define DHn  64
#define DFFn 4096
#define Bn   2
#define Tn   2048
#define MTn  (Bn * Tn)          // 4096 rows total
#define N3E  (3 * En)           // 3072 packed qkv

// ---------------- scratch (device globals: no allocation allowed) --------
__device__ float g_h  [MTn * En];             // ln1 out (tf32-rounded)
__device__ float g_qkv[(size_t)MTn * N3E];    // packed q|k|v (tf32-rounded)
__device__ float g_o  [MTn * En];             // attention out (tf32-rounded)
__device__ float g_x2 [MTn * En];             // x + sa (full fp32)
__device__ float g_h2 [MTn * En];             // ln2 out (tf32-rounded)
__device__ float g_ff [(size_t)MTn * DFFn];   // relu(h2 W1 + b1) (tf32-rounded)
__device__ float g_wqkvt[(size_t)N3E * En];   // [Wq^T; Wk^T; Wv^T] (tf32-rounded)
__device__ float g_wot  [En * En];            // Wo^T (tf32-rounded)
__device__ float g_w1t  [(size_t)DFFn * En];  // W1^T (tf32-rounded)
__device__ float g_w2t  [(size_t)En * DFFn];  // W2^T (tf32-rounded)

// =====================================================================
// helpers
// =====================================================================
__device__ __forceinline__ float tf32_rna(float x) {
    float y;
    asm("cvt.rna.tf32.f32 %0, %1;" : "=f"(y) : "f"(x));
    return y;
}

__device__ __forceinline__ void mma_tf32(float* d, const uint32_t* a, const uint32_t* b) {
    asm volatile(
        "mma.sync.aligned.m16n8k8.row.col.f32.tf32.tf32.f32 "
        "{%0,%1,%2,%3}, {%4,%5,%6,%7}, {%8,%9}, {%0,%1,%2,%3};"
        : "+f"(d[0]), "+f"(d[1]), "+f"(d[2]), "+f"(d[3])
        : "r"(a[0]), "r"(a[1]), "r"(a[2]), "r"(a[3]),
          "r"(b[0]), "r"(b[1]));
}

__device__ __forceinline__ uint32_t smem_u32(const void* p) {
    uint32_t a;
    asm("{ .reg .u64 t; cvta.to.shared.u64 t, %1; cvt.u32.u64 %0, t; }"
        : "=r"(a) : "l"(p));
    return a;
}

__device__ __forceinline__ void cp_async16(uint32_t saddr, const void* gptr) {
    asm volatile("cp.async.cg.shared.global [%0], [%1], 16;"
                 :: "r"(saddr), "l"(gptr) : "memory");
}
__device__ __forceinline__ void cp_commit() {
    asm volatile("cp.async.commit_group;" ::: "memory");
}
template<int N>
__device__ __forceinline__ void cp_wait() {
    asm volatile("cp.async.wait_group %0;" :: "n"(N) : "memory");
}

// =====================================================================
// transposes (rna folded in: weights become tf32-exact in gmem)
// =====================================================================
__global__ void transpose_kernel(const float* __restrict__ in,
                                 float* __restrict__ out, int R, int C)
{
    __shared__ float t[32][33];
    const int c  = blockIdx.x * 32 + threadIdx.x;
    const int r0 = blockIdx.y * 32;
    #pragma unroll
    for (int i = threadIdx.y; i < 32; i += 8)
        t[i][threadIdx.x] = in[(size_t)(r0 + i) * C + c];
    __syncthreads();
    const int rr = r0 + threadIdx.x;
    const int cb = blockIdx.x * 32;
    #pragma unroll
    for (int i = threadIdx.y; i < 32; i += 8)
        out[(size_t)(cb + i) * R + rr] = tf32_rna(t[threadIdx.x][i]);
}

// four square ExE transposes in one launch (grid.z selects matrix)
__global__ void transpose_sq4(const float* __restrict__ s0, const float* __restrict__ s1,
                              const float* __restrict__ s2, const float* __restrict__ s3,
                              float* __restrict__ d0, float* __restrict__ d1,
                              float* __restrict__ d2, float* __restrict__ d3)
{
    __shared__ float t[32][33];
    const float* in; float* out;
    switch (blockIdx.z) {
        case 0:  in = s0; out = d0; break;
        case 1:  in = s1; out = d1; break;
        case 2:  in = s2; out = d2; break;
        default: in = s3; out = d3; break;
    }
    const int c  = blockIdx.x * 32 + threadIdx.x;
    const int r0 = blockIdx.y * 32;
    #pragma unroll
    for (int i = threadIdx.y; i < 32; i += 8)
        t[i][threadIdx.x] = in[(size_t)(r0 + i) * En + c];
    __syncthreads();
    const int rr = r0 + threadIdx.x;
    const int cb = blockIdx.x * 32;
    #pragma unroll
    for (int i = threadIdx.y; i < 32; i += 8)
        out[(size_t)(cb + i) * En + rr] = tf32_rna(t[threadIdx.x][i]);
}

// =====================================================================
// LayerNorm (output tf32-rounded: it only feeds GEMMs)
// =====================================================================
__global__ void ln_kernel(const float* __restrict__ x,
                          const float* __restrict__ g,
                          const float* __restrict__ be,
                          float* __restrict__ out)
{
    __shared__ float red[2][8];
    const int row = blockIdx.x;
    const int t   = threadIdx.x;

    const float4 xv = reinterpret_cast<const float4*>(x + (size_t)row * En)[t];
    float s  = xv.x + xv.y + xv.z + xv.w;
    float ss = xv.x*xv.x + xv.y*xv.y + xv.z*xv.z + xv.w*xv.w;

    #pragma unroll
    for (int off = 16; off; off >>= 1) {
        s  += __shfl_xor_sync(0xffffffffu, s,  off);
        ss += __shfl_xor_sync(0xffffffffu, ss, off);
    }
    if ((t & 31) == 0) { red[0][t >> 5] = s; red[1][t >> 5] = ss; }
    __syncthreads();
    s = 0.f; ss = 0.f;
    #pragma unroll
    for (int w = 0; w < 8; w++) { s += red[0][w]; ss += red[1][w]; }

    const float mu  = s * (1.0f / En);
    const float var = ss * (1.0f / En) - mu * mu;
    const float inv = rsqrtf(var + 1e-5f);

    const float4 gv = reinterpret_cast<const float4*>(g)[t];
    const float4 bv = reinterpret_cast<const float4*>(be)[t];
    float4 ov;
    ov.x = tf32_rna((xv.x - mu) * inv * gv.x + bv.x);
    ov.y = tf32_rna((xv.y - mu) * inv * gv.y + bv.y);
    ov.z = tf32_rna((xv.z - mu) * inv * gv.z + bv.z);
    ov.w = tf32_rna((xv.w - mu) * inv * gv.w + bv.w);
    reinterpret_cast<float4*>(out + (size_t)row * En)[t] = ov;
}

// =====================================================================
// TF32 mma.sync GEMM with 3-stage cp.async pipeline.
// C[M,N] = A[M,K] * Bt[N,K]^T  (+ epilogue). Inputs pre-rounded to tf32.
// CTA 128x128, 8 warps (2m x 4n), KC=32, PAD=36.
// EPI: 0 none (round out), 1 +bias+ReLU (round out), 2 +bias+residual (raw)
// =====================================================================
#define KC   32
#define GPAD 36
#define STG_FLOATS (2 * 128 * GPAD)          // 9216 floats per stage (A+B)
#define STG_BYTES  (STG_FLOATS * 4)          // 36864
#define GEMM_SMEM  (3 * STG_BYTES)           // 110592

template<int EPI>
__global__ void __launch_bounds__(256, 2)
gemm_mma(const float* __restrict__ A, const float* __restrict__ Bt,
         float* __restrict__ C, int K, int Ntot,
         const float* __restrict__ bias, const float* __restrict__ resid)
{
    extern __shared__ float smg[];
    const uint32_t sbase = smem_u32(smg);

    const int tid  = threadIdx.x;
    const int lane = tid & 31;
    const int wid  = tid >> 5;
    const int wm   = wid >> 2;       // 0..1
    const int wn   = wid & 3;        // 0..3
    const int grp  = lane >> 2;      // 0..7
    const int tig  = lane & 3;       // 0..3

    const int m0 = blockIdx.y * 128;
    const int n0 = blockIdx.x * 128;

    const float* Ag = A  + (size_t)m0 * K;
    const float* Bg = Bt + (size_t)n0 * K;

    const int r0 = tid >> 3;          // 0..31 (+32p)
    const int c0 = (tid & 7) * 4;     // 0..28

    float acc[4][4][4];
    #pragma unroll
    for (int mt = 0; mt < 4; mt++)
        #pragma unroll
        for (int nt = 0; nt < 4; nt++)
            #pragma unroll
            for (int e = 0; e < 4; e++) acc[mt][nt][e] = 0.f;

    auto issue = [&](int stg, int k0) {
        const uint32_t ab = sbase + (uint32_t)stg * STG_BYTES;
        #pragma unroll
        for (int p = 0; p < 4; p++) {
            const int r = r0 + p * 32;
            cp_async16(ab + (uint32_t)(r * GPAD + c0) * 4u,
                       Ag + (size_t)r * K + k0 + c0);
            cp_async16(ab + 18432u + (uint32_t)(r * GPAD + c0) * 4u,
                       Bg + (size_t)r * K + k0 + c0);
        }
        cp_commit();
    };

    const int nch = K / KC;      // >= 32 always here

    issue(0, 0);
    issue(1, KC);

    int stg = 0;
    for (int ch = 0; ch < nch; ch++) {
        if (ch + 1 < nch) cp_wait<1>(); else cp_wait<0>();
        __syncthreads();
        if (ch + 2 < nch) {
            int ns = stg + 2; if (ns >= 3) ns -= 3;
            issue(ns, (ch + 2) * KC);
        }

        const float* As = smg + stg * STG_FLOATS;
        const float* Bs = As + 4608;

        #pragma unroll
        for (int ks = 0; ks < 4; ks++) {
            const int kb = ks * 8;
            uint32_t afr[4][4], bfr[4][2];
            #pragma unroll
            for (int mt = 0; mt < 4; mt++) {
                const float* base = &As[(wm * 64 + mt * 16) * GPAD + kb];
                afr[mt][0] = __float_as_uint(base[grp * GPAD + tig]);
                afr[mt][1] = __float_as_uint(base[(grp + 8) * GPAD + tig]);
                afr[mt][2] = __float_as_uint(base[grp * GPAD + tig + 4]);
                afr[mt][3] = __float_as_uint(base[(grp + 8) * GPAD + tig + 4]);
            }
            #pragma unroll
            for (int nt = 0; nt < 4; nt++) {
                const float* base = &Bs[(wn * 32 + nt * 8) * GPAD + kb];
                bfr[nt][0] = __float_as_uint(base[grp * GPAD + tig]);
                bfr[nt][1] = __float_as_uint(base[grp * GPAD + tig + 4]);
            }
            #pragma unroll
            for (int mt = 0; mt < 4; mt++)
                #pragma unroll
                for (int nt = 0; nt < 4; nt++)
                    mma_tf32(acc[mt][nt], afr[mt], bfr[nt]);
        }

        if (++stg >= 3) stg = 0;
    }

    // -------- epilogue
    #pragma unroll
    for (int mt = 0; mt < 4; mt++) {
        #pragma unroll
        for (int half = 0; half < 2; half++) {
            const int m = m0 + wm * 64 + mt * 16 + grp + half * 8;
            #pragma unroll
            for (int nt = 0; nt < 4; nt++) {
                const int n = n0 + wn * 32 + nt * 8 + tig * 2;
                float2 v;
                v.x = acc[mt][nt][half * 2 + 0];
                v.y = acc[mt][nt][half * 2 + 1];
                if (EPI >= 1) {
                    const float2 bb = *reinterpret_cast<const float2*>(bias + n);
                    v.x += bb.x; v.y += bb.y;
                }
                if (EPI == 1) {
                    v.x = fmaxf(v.x, 0.f); v.y = fmaxf(v.y, 0.f);
                }
                if (EPI == 2) {
                    const float2 rr = *reinterpret_cast<const float2*>(
                        resid + (size_t)m * Ntot + n);
                    v.x += rr.x; v.y += rr.y;
                } else {
                    // output feeds another GEMM / attention: pre-round to tf32
                    v.x = tf32_rna(v.x); v.y = tf32_rna(v.y);
                }
                *reinterpret_cast<float2*>(C + (size_t)m * Ntot + n) = v;
            }
        }
    }
}

// =====================================================================
// Tensor-core flash attention (causal, tf32 mma.sync), cp.async K/V
// double buffer. BM=128 (8 warps x 16 q rows), BN=64, DH=64.
// qkv is pre-rounded tf32 (QKV-GEMM epilogue) -> raw copies, no cvt.
// =====================================================================
#define QPAD 68
#define KPAD 68
#define VPAD 72
#define ASTG_FLOATS (64 * KPAD + 64 * VPAD)   // 8960
#define ASTG_BYTES  (ASTG_FLOATS * 4)         // 35840
#define AKBYTES     (64 * KPAD * 4)           // 17408
#define ATTN_SMEM   (2 * ASTG_BYTES)          // 71680

__global__ void __launch_bounds__(256)
attn_tc(const float* __restrict__ qkv, float* __restrict__ o)
{
    extern __shared__ float sma[];
    const uint32_t sbase = smem_u32(sma);

    const int qt   = (gridDim.x - 1) - blockIdx.x;   // heavy tiles first
    const int h    = blockIdx.y;
    const int b    = blockIdx.z;
    const int tid  = threadIdx.x;
    const int lane = tid & 31;
    const int w    = tid >> 5;
    const int grp  = lane >> 2;
    const int tig  = lane & 3;

    const int q0 = qt * 128;
    const size_t base = (size_t)b * Tn * N3E + (size_t)h * DHn;

    // ---- stage Q (scaled; values tf32-exact, scale is 2^-5 => exact) ----
    #pragma unroll
    for (int p = 0; p < 8; p++) {
        const int idx = tid + p * 256;
        const int r = idx >> 4, c4 = (idx & 15) << 2;
        float4 v = *reinterpret_cast<const float4*>(
            qkv + base + (size_t)(q0 + r) * N3E + c4);
        v.x *= 0.03125f; v.y *= 0.03125f; v.z *= 0.03125f; v.w *= 0.03125f;
        *reinterpret_cast<float4*>(&sma[r * QPAD + c4]) = v;
    }
    __syncthreads();

    // ---- extract Q fragments ----
    uint32_t qa[8][4];
    {
        const float* qrow_lo = &sma[(w * 16 + grp) * QPAD];
        const float* qrow_hi = qrow_lo + 8 * QPAD;
        #pragma unroll
        for (int ks = 0; ks < 8; ks++) {
            qa[ks][0] = __float_as_uint(qrow_lo[ks * 8 + tig]);
            qa[ks][1] = __float_as_uint(qrow_hi[ks * 8 + tig]);
            qa[ks][2] = __float_as_uint(qrow_lo[ks * 8 + tig + 4]);
            qa[ks][3] = __float_as_uint(qrow_hi[ks * 8 + tig + 4]);
        }
    }
    __syncthreads();   // Q area free before cp.async overwrites it

    auto issue_kv = [&](int kt, int buf) {
        const int k0 = kt * 64;
        const uint32_t kb = sbase + (uint32_t)buf * ASTG_BYTES;
        #pragma unroll
        for (int p = 0; p < 4; p++) {
            const int idx = tid + p * 256;
            const int r = idx >> 4, c4 = (idx & 15) << 2;
            cp_async16(kb + (uint32_t)(r * KPAD + c4) * 4u,
                       qkv + base + En + (size_t)(k0 + r) * N3E + c4);
            cp_async16(kb + AKBYTES + (uint32_t)(r * VPAD + c4) * 4u,
                       qkv + base + 2 * En + (size_t)(k0 + r) * N3E + c4);
        }
        cp_commit();
    };

    float o_acc[8][4];
    #pragma unroll
    for (int nt = 0; nt < 8; nt++)
        #pragma unroll
        for (int e = 0; e < 4; e++) o_acc[nt][e] = 0.f;
    float m_lo = -1e30f, m_hi = -1e30f, l_lo = 0.f, l_hi = 0.f;

    const int nkt   = 2 * qt + 2;
    const int lr_lo = w * 16 + grp;
    const int lr_hi = lr_lo + 8;
    const int src   = (lane & ~3) | (tig >> 1);
    const int src2  = src + 2;

    issue_kv(0, 0);

    for (int kt = 0; kt < nkt; kt++) {
        const int buf = kt & 1;
        const int k0  = kt * 64;

        cp_wait<0>();       // tile kt landed (only pending group)
        __syncthreads();    // visible to all; all warps done with buf^1
        if (kt + 1 < nkt) issue_kv(kt + 1, buf ^ 1);

        const float* Ks = sma + buf * ASTG_FLOATS;
        const float* Vs = Ks + 64 * KPAD;

        const bool skip = (kt == nkt - 1) && (w < 4);
        if (!skip) {
            // ---- S = (Q*scale) @ K^T ----
            float s[8][4];
            #pragma unroll
            for (int nt = 0; nt < 8; nt++)
                #pragma unroll
                for (int e = 0; e < 4; e++) s[nt][e] = 0.f;

            #pragma unroll
            for (int nt = 0; nt < 8; nt++) {
                const float* kbase = &Ks[(nt * 8 + grp) * KPAD];
                #pragma unroll
                for (int ks = 0; ks < 8; ks++) {
                    uint32_t bfr[2];
                    bfr[0] = __float_as_uint(kbase[ks * 8 + tig]);
                    bfr[1] = __float_as_uint(kbase[ks * 8 + tig + 4]);
                    mma_tf32(s[nt], qa[ks], bfr);
                }
            }

            // ---- causal mask (only last two kv tiles can clip) ----
            if (kt >= nkt - 2) {
                const int koff = k0 - q0;
                #pragma unroll
                for (int nt = 0; nt < 8; nt++)
                    #pragma unroll
                    for (int e = 0; e < 2; e++) {
                        const int lc = koff + nt * 8 + 2 * tig + e;
                        if (lc > lr_lo) s[nt][e]     = -1e30f;
                        if (lc > lr_hi) s[nt][e + 2] = -1e30f;
                    }
            }

            // ---- online softmax ----
            float mx_lo = -1e30f, mx_hi = -1e30f;
            #pragma unroll
            for (int nt = 0; nt < 8; nt++) {
                mx_lo = fmaxf(mx_lo, fmaxf(s[nt][0], s[nt][1]));
                mx_hi = fmaxf(mx_hi, fmaxf(s[nt][2], s[nt][3]));
            }
            #pragma unroll
            for (int off = 1; off <= 2; off <<= 1) {
                mx_lo = fmaxf(mx_lo, __shfl_xor_sync(0xffffffffu, mx_lo, off));
                mx_hi = fmaxf(mx_hi, __shfl_xor_sync(0xffffffffu, mx_hi, off));
            }
            const float mn_lo = fmaxf(m_lo, mx_lo);
            const float mn_hi = fmaxf(m_hi, mx_hi);
            const float corr_lo = __expf(m_lo - mn_lo);
            const float corr_hi = __expf(m_hi - mn_hi);
            m_lo = mn_lo; m_hi = mn_hi;

            float rs_lo = 0.f, rs_hi = 0.f;
            #pragma unroll
            for (int nt = 0; nt < 8; nt++) {
                s[nt][0] = __expf(s[nt][0] - mn_lo);
                s[nt][1] = __expf(s[nt][1] - mn_lo);
                s[nt][2] = __expf(s[nt][2] - mn_hi);
                s[nt][3] = __expf(s[nt][3] - mn_hi);
                rs_lo += s[nt][0] + s[nt][1];
                rs_hi += s[nt][2] + s[nt][3];
            }
            #pragma unroll
            for (int off = 1; off <= 2; off <<= 1) {
                rs_lo += __shfl_xor_sync(0xffffffffu, rs_lo, off);
                rs_hi += __shfl_xor_sync(0xffffffffu, rs_hi, off);
            }
            l_lo = l_lo * corr_lo + rs_lo;
            l_hi = l_hi * corr_hi + rs_hi;
            #pragma unroll
            for (int nt = 0; nt < 8; nt++) {
                o_acc[nt][0] *= corr_lo; o_acc[nt][1] *= corr_lo;
                o_acc[nt][2] *= corr_hi; o_acc[nt][3] *= corr_hi;
            }

            // ---- P -> tf32 ----
            #pragma unroll
            for (int nt = 0; nt < 8; nt++)
                #pragma unroll
                for (int e = 0; e < 4; e++)
                    s[nt][e] = tf32_rna(s[nt][e]);

            // ---- O += P @ V (A frags via quad shfl) ----
            #pragma unroll
            for (int ks = 0; ks < 8; ks++) {
                const uint32_t p0 = __float_as_uint(s[ks][0]);
                const uint32_t p1 = __float_as_uint(s[ks][1]);
                const uint32_t p2 = __float_as_uint(s[ks][2]);
                const uint32_t p3 = __float_as_uint(s[ks][3]);
                const uint32_t v0 = __shfl_sync(0xffffffffu, p0, src);
                const uint32_t v1 = __shfl_sync(0xffffffffu, p1, src);
                const uint32_t v2 = __shfl_sync(0xffffffffu, p2, src);
                const uint32_t v3 = __shfl_sync(0xffffffffu, p3, src);
                const uint32_t w0 = __shfl_sync(0xffffffffu, p0, src2);
                const uint32_t w1 = __shfl_sync(0xffffffffu, p1, src2);
                const uint32_t w2 = __shfl_sync(0xffffffffu, p2, src2);
                const uint32_t w3 = __shfl_sync(0xffffffffu, p3, src2);
                uint32_t a[4];
                a[0] = (tig & 1) ? v1 : v0;
                a[1] = (tig & 1) ? v3 : v2;
                a[2] = (tig & 1) ? w1 : w0;
                a[3] = (tig & 1) ? w3 : w2;

                const float* vb0 = &Vs[(ks * 8 + tig) * VPAD];
                const float* vb1 = &Vs[(ks * 8 + tig + 4) * VPAD];
                #pragma unroll
                for (int nt = 0; nt < 8; nt++) {
                    uint32_t bfr[2];
                    bfr[0] = __float_as_uint(vb0[nt * 8 + grp]);
                    bfr[1] = __float_as_uint(vb1[nt * 8 + grp]);
                    mma_tf32(o_acc[nt], a, bfr);
                }
            }
        }
    }

    // ---- normalize & write (round: o feeds the Wo GEMM) ----
    const float inv_lo = 1.0f / l_lo;
    const float inv_hi = 1.0f / l_hi;
    const size_t obase = (size_t)b * Tn * En + (size_t)h * DHn;
    const int r_lo = q0 + w * 16 + grp;
    #pragma unroll
    for (int nt = 0; nt < 8; nt++) {
        const int c = nt * 8 + 2 * tig;
        float2 vlo, vhi;
        vlo.x = tf32_rna(o_acc[nt][0] * inv_lo);
        vlo.y = tf32_rna(o_acc[nt][1] * inv_lo);
        vhi.x = tf32_rna(o_acc[nt][2] * inv_hi);
        vhi.y = tf32_rna(o_acc[nt][3] * inv_hi);
        *reinterpret_cast<float2*>(o + obase + (size_t)r_lo * En + c)       = vlo;
        *reinterpret_cast<float2*>(o + obase + (size_t)(r_lo + 8) * En + c) = vhi;
    }
}

// =====================================================================
// launch
// =====================================================================
extern "C" void kernel_launch(void* const* d_in, const int* in_sizes, int n_in,
                              void* d_out, int out_size)
{
    const float* x   = (const float*)d_in[0];
    const float* Wq  = (const float*)d_in[1];
    const float* Wk  = (const float*)d_in[2];
    const float* Wv  = (const float*)d_in[3];
    const float* Wo  = (const float*)d_in[4];
    const float* bo  = (const float*)d_in[5];
    const float* W1  = (const float*)d_in[6];
    const float* b1  = (const float*)d_in[7];
    const float* W2  = (const float*)d_in[8];
    const float* b2  = (const float*)d_in[9];
    const float* g1  = (const float*)d_in[10];
    const float* be1 = (const float*)d_in[11];
    const float* g2  = (const float*)d_in[12];
    const float* be2 = (const float*)d_in[13];
    float* out = (float*)d_out;
    (void)in_sizes; (void)n_in; (void)out_size;

    float *h, *qkv, *o, *x2, *h2, *ff, *wqkvt, *wot, *w1t, *w2t;
    cudaGetSymbolAddress((void**)&h,     g_h);
    cudaGetSymbolAddress((void**)&qkv,   g_qkv);
    cudaGetSymbolAddress((void**)&o,     g_o);
    cudaGetSymbolAddress((void**)&x2,    g_x2);
    cudaGetSymbolAddress((void**)&h2,    g_h2);
    cudaGetSymbolAddress((void**)&ff,    g_ff);
    cudaGetSymbolAddress((void**)&wqkvt, g_wqkvt);
    cudaGetSymbolAddress((void**)&wot,   g_wot);
    cudaGetSymbolAddress((void**)&w1t,   g_w1t);
    cudaGetSymbolAddress((void**)&w2t,   g_w2t);

    cudaFuncSetAttribute(attn_tc,
                         cudaFuncAttributeMaxDynamicSharedMemorySize, ATTN_SMEM);
    cudaFuncSetAttribute(gemm_mma<0>,
                         cudaFuncAttributeMaxDynamicSharedMemorySize, GEMM_SMEM);
    cudaFuncSetAttribute(gemm_mma<1>,
                         cudaFuncAttributeMaxDynamicSharedMemorySize, GEMM_SMEM);
    cudaFuncSetAttribute(gemm_mma<2>,
                         cudaFuncAttributeMaxDynamicSharedMemorySize, GEMM_SMEM);

    const dim3 tb(32, 8);
    // weights -> K-major, tf32-rounded
    transpose_sq4<<<dim3(En / 32, En / 32, 4), tb>>>(
        Wq, Wk, Wv, Wo,
        wqkvt, wqkvt + En * En, wqkvt + 2 * En * En, wot);
    transpose_kernel<<<dim3(DFFn / 32, En / 32), tb>>>(W1, w1t, En,   DFFn);
    transpose_kernel<<<dim3(En / 32, DFFn / 32), tb>>>(W2, w2t, DFFn, En);

    // 1. ln1 (tf32-rounded out)
    ln_kernel<<<MTn, 256>>>(x, g1, be1, h);
    // 2. fused QKV GEMM (rounded out)
    gemm_mma<0><<<dim3(N3E / 128, MTn / 128), 256, GEMM_SMEM>>>(
        h, wqkvt, qkv, En, N3E, nullptr, nullptr);
    // 3. attention (tensor core, async K/V; rounded out)
    attn_tc<<<dim3(Tn / 128, Hn, Bn), 256, ATTN_SMEM>>>(qkv, o);
    // 4. out proj + bias + residual -> x2 (raw fp32)
    gemm_mma<2><<<dim3(En / 128, MTn / 128), 256, GEMM_SMEM>>>(
        o, wot, x2, En, En, bo, x);
    // 5. ln2 (rounded out)
    ln_kernel<<<MTn, 256>>>(x2, g2, be2, h2);
    // 6. FFN1 (+bias, ReLU; rounded out)
    gemm_mma<1><<<dim3(DFFn / 128, MTn / 128), 256, GEMM_SMEM>>>(
        h2, w1t, ff, En, DFFn, b1, nullptr);
    // 7. FFN2 (+bias +residual) -> out (raw fp32)
    gemm_mma<2><<<dim3(En / 128, MTn / 128), 256, GEMM_SMEM>>>(
        ff, w2t, out, DFFn, En, b2, x2);
}

// round 17
// speedup vs baseline: 1.0011x; 1.0011x over previous
#include <cuda_runtime.h>
#include <cstdint>

// ---------------- problem constants ----------------
#define En   1024
#define Hn   16
#define DHn  64
#define DFFn 4096
#define Bn   2
#define Tn   2048
#define MTn  (Bn * Tn)          // 4096 rows total
#define N3E  (3 * En)           // 3072 packed qkv

// ---------------- scratch (device globals: no allocation allowed) --------
__device__ float g_h  [MTn * En];             // ln1 out (tf32-rounded)
__device__ float g_qkv[(size_t)MTn * N3E];    // packed q|k|v (tf32-rounded)
__device__ float g_o  [MTn * En];             // attention out (tf32-rounded)
__device__ float g_x2 [MTn * En];             // x + sa (full fp32)
__device__ float g_h2 [MTn * En];             // ln2 out (tf32-rounded)
__device__ float g_ff [(size_t)MTn * DFFn];   // relu(h2 W1 + b1) (tf32-rounded)
__device__ float g_wqkvt[(size_t)N3E * En];   // [Wq^T; Wk^T; Wv^T] (tf32-rounded)
__device__ float g_wot  [En * En];            // Wo^T (tf32-rounded)
__device__ float g_w1t  [(size_t)DFFn * En];  // W1^T (tf32-rounded)
__device__ float g_w2t  [(size_t)En * DFFn];  // W2^T (tf32-rounded)

// =====================================================================
// helpers
// =====================================================================
__device__ __forceinline__ float tf32_rna(float x) {
    float y;
    asm("cvt.rna.tf32.f32 %0, %1;" : "=f"(y) : "f"(x));
    return y;
}

__device__ __forceinline__ void mma_tf32(float* d, const uint32_t* a, const uint32_t* b) {
    asm volatile(
        "mma.sync.aligned.m16n8k8.row.col.f32.tf32.tf32.f32 "
        "{%0,%1,%2,%3}, {%4,%5,%6,%7}, {%8,%9}, {%0,%1,%2,%3};"
        : "+f"(d[0]), "+f"(d[1]), "+f"(d[2]), "+f"(d[3])
        : "r"(a[0]), "r"(a[1]), "r"(a[2]), "r"(a[3]),
          "r"(b[0]), "r"(b[1]));
}

__device__ __forceinline__ uint32_t smem_u32(const void* p) {
    uint32_t a;
    asm("{ .reg .u64 t; cvta.to.shared.u64 t, %1; cvt.u32.u64 %0, t; }"
        : "=r"(a) : "l"(p));
    return a;
}

__device__ __forceinline__ void cp_async16(uint32_t saddr, const void* gptr) {
    asm volatile("cp.async.cg.shared.global [%0], [%1], 16;"
                 :: "r"(saddr), "l"(gptr) : "memory");
}
__device__ __forceinline__ void cp_commit() {
    asm volatile("cp.async.commit_group;" ::: "memory");
}
template<int N>
__device__ __forceinline__ void cp_wait() {
    asm volatile("cp.async.wait_group %0;" :: "n"(N) : "memory");
}

// =====================================================================
// transposes (rna folded in: weights become tf32-exact in gmem)
// =====================================================================
__global__ void transpose_kernel(const float* __restrict__ in,
                                 float* __restrict__ out, int R, int C)
{
    __shared__ float t[32][33];
    const int c  = blockIdx.x * 32 + threadIdx.x;
    const int r0 = blockIdx.y * 32;
    #pragma unroll
    for (int i = threadIdx.y; i < 32; i += 8)
        t[i][threadIdx.x] = in[(size_t)(r0 + i) * C + c];
    __syncthreads();
    const int rr = r0 + threadIdx.x;
    const int cb = blockIdx.x * 32;
    #pragma unroll
    for (int i = threadIdx.y; i < 32; i += 8)
        out[(size_t)(cb + i) * R + rr] = tf32_rna(t[threadIdx.x][i]);
}

// four square ExE transposes in one launch (grid.z selects matrix)
__global__ void transpose_sq4(const float* __restrict__ s0, const float* __restrict__ s1,
                              const float* __restrict__ s2, const float* __restrict__ s3,
                              float* __restrict__ d0, float* __restrict__ d1,
                              float* __restrict__ d2, float* __restrict__ d3)
{
    __shared__ float t[32][33];
    const float* in; float* out;
    switch (blockIdx.z) {
        case 0:  in = s0; out = d0; break;
        case 1:  in = s1; out = d1; break;
        case 2:  in = s2; out = d2; break;
        default: in = s3; out = d3; break;
    }
    const int c  = blockIdx.x * 32 + threadIdx.x;
    const int r0 = blockIdx.y * 32;
    #pragma unroll
    for (int i = threadIdx.y; i < 32; i += 8)
        t[i][threadIdx.x] = in[(size_t)(r0 + i) * En + c];
    __syncthreads();
    const int rr = r0 + threadIdx.x;
    const int cb = blockIdx.x * 32;
    #pragma unroll
    for (int i = threadIdx.y; i < 32; i += 8)
        out[(size_t)(cb + i) * En + rr] = tf32_rna(t[threadIdx.x][i]);
}

// =====================================================================
// LayerNorm (output tf32-rounded: it only feeds GEMMs)
// =====================================================================
__global__ void ln_kernel(const float* __restrict__ x,
                          const float* __restrict__ g,
                          const float* __restrict__ be,
                          float* __restrict__ out)
{
    __shared__ float red[2][8];
    const int row = blockIdx.x;
    const int t   = threadIdx.x;

    const float4 xv = reinterpret_cast<const float4*>(x + (size_t)row * En)[t];
    float s  = xv.x + xv.y + xv.z + xv.w;
    float ss = xv.x*xv.x + xv.y*xv.y + xv.z*xv.z + xv.w*xv.w;

    #pragma unroll
    for (int off = 16; off; off >>= 1) {
        s  += __shfl_xor_sync(0xffffffffu, s,  off);
        ss += __shfl_xor_sync(0xffffffffu, ss, off);
    }
    if ((t & 31) == 0) { red[0][t >> 5] = s; red[1][t >> 5] = ss; }
    __syncthreads();
    s = 0.f; ss = 0.f;
    #pragma unroll
    for (int w = 0; w < 8; w++) { s += red[0][w]; ss += red[1][w]; }

    const float mu  = s * (1.0f / En);
    const float var = ss * (1.0f / En) - mu * mu;
    const float inv = rsqrtf(var + 1e-5f);

    const float4 gv = reinterpret_cast<const float4*>(g)[t];
    const float4 bv = reinterpret_cast<const float4*>(be)[t];
    float4 ov;
    ov.x = tf32_rna((xv.x - mu) * inv * gv.x + bv.x);
    ov.y = tf32_rna((xv.y - mu) * inv * gv.y + bv.y);
    ov.z = tf32_rna((xv.z - mu) * inv * gv.z + bv.z);
    ov.w = tf32_rna((xv.w - mu) * inv * gv.w + bv.w);
    reinterpret_cast<float4*>(out + (size_t)row * En)[t] = ov;
}

// =====================================================================
// TF32 mma.sync GEMM with 3-stage cp.async pipeline.
// C[M,N] = A[M,K] * Bt[N,K]^T  (+ epilogue). Inputs pre-rounded to tf32.
// CTA 128x128, 8 warps (2m x 4n), KC=32, PAD=36.
// EPI: 0 none (round out), 1 +bias+ReLU (round out), 2 +bias+residual (raw)
// =====================================================================
#define KC   32
#define GPAD 36
#define STG_FLOATS (2 * 128 * GPAD)          // 9216 floats per stage (A+B)
#define STG_BYTES  (STG_FLOATS * 4)          // 36864
#define GEMM_SMEM  (3 * STG_BYTES)           // 110592

template<int EPI>
__global__ void __launch_bounds__(256, 2)
gemm_mma(const float* __restrict__ A, const float* __restrict__ Bt,
         float* __restrict__ C, int K, int Ntot,
         const float* __restrict__ bias, const float* __restrict__ resid)
{
    extern __shared__ float smg[];
    const uint32_t sbase = smem_u32(smg);

    const int tid  = threadIdx.x;
    const int lane = tid & 31;
    const int wid  = tid >> 5;
    const int wm   = wid >> 2;       // 0..1
    const int wn   = wid & 3;        // 0..3
    const int grp  = lane >> 2;      // 0..7
    const int tig  = lane & 3;       // 0..3

    const int m0 = blockIdx.y * 128;
    const int n0 = blockIdx.x * 128;

    const float* Ag = A  + (size_t)m0 * K;
    const float* Bg = Bt + (size_t)n0 * K;

    const int r0 = tid >> 3;          // 0..31 (+32p)
    const int c0 = (tid & 7) * 4;     // 0..28

    float acc[4][4][4];
    #pragma unroll
    for (int mt = 0; mt < 4; mt++)
        #pragma unroll
        for (int nt = 0; nt < 4; nt++)
            #pragma unroll
            for (int e = 0; e < 4; e++) acc[mt][nt][e] = 0.f;

    auto issue = [&](int stg, int k0) {
        const uint32_t ab = sbase + (uint32_t)stg * STG_BYTES;
        #pragma unroll
        for (int p = 0; p < 4; p++) {
            const int r = r0 + p * 32;
            cp_async16(ab + (uint32_t)(r * GPAD + c0) * 4u,
                       Ag + (size_t)r * K + k0 + c0);
            cp_async16(ab + 18432u + (uint32_t)(r * GPAD + c0) * 4u,
                       Bg + (size_t)r * K + k0 + c0);
        }
        cp_commit();
    };

    const int nch = K / KC;      // >= 32 always here

    issue(0, 0);
    issue(1, KC);

    int stg = 0;
    for (int ch = 0; ch < nch; ch++) {
        if (ch + 1 < nch) cp_wait<1>(); else cp_wait<0>();
        __syncthreads();
        if (ch + 2 < nch) {
            int ns = stg + 2; if (ns >= 3) ns -= 3;
            issue(ns, (ch + 2) * KC);
        }

        const float* As = smg + stg * STG_FLOATS;
        const float* Bs = As + 4608;

        #pragma unroll
        for (int ks = 0; ks < 4; ks++) {
            const int kb = ks * 8;
            uint32_t afr[4][4], bfr[4][2];
            #pragma unroll
            for (int mt = 0; mt < 4; mt++) {
                const float* base = &As[(wm * 64 + mt * 16) * GPAD + kb];
                afr[mt][0] = __float_as_uint(base[grp * GPAD + tig]);
                afr[mt][1] = __float_as_uint(base[(grp + 8) * GPAD + tig]);
                afr[mt][2] = __float_as_uint(base[grp * GPAD + tig + 4]);
                afr[mt][3] = __float_as_uint(base[(grp + 8) * GPAD + tig + 4]);
            }
            #pragma unroll
            for (int nt = 0; nt < 4; nt++) {
                const float* base = &Bs[(wn * 32 + nt * 8) * GPAD + kb];
                bfr[nt][0] = __float_as_uint(base[grp * GPAD + tig]);
                bfr[nt][1] = __float_as_uint(base[grp * GPAD + tig + 4]);
            }
            #pragma unroll
            for (int mt = 0; mt < 4; mt++)
                #pragma unroll
                for (int nt = 0; nt < 4; nt++)
                    mma_tf32(acc[mt][nt], afr[mt], bfr[nt]);
        }

        if (++stg >= 3) stg = 0;
    }

    // -------- epilogue
    #pragma unroll
    for (int mt = 0; mt < 4; mt++) {
        #pragma unroll
        for (int half = 0; half < 2; half++) {
            const int m = m0 + wm * 64 + mt * 16 + grp + half * 8;
            #pragma unroll
            for (int nt = 0; nt < 4; nt++) {
                const int n = n0 + wn * 32 + nt * 8 + tig * 2;
                float2 v;
                v.x = acc[mt][nt][half * 2 + 0];
                v.y = acc[mt][nt][half * 2 + 1];
                if (EPI >= 1) {
                    const float2 bb = *reinterpret_cast<const float2*>(bias + n);
                    v.x += bb.x; v.y += bb.y;
                }
                if (EPI == 1) {
                    v.x = fmaxf(v.x, 0.f); v.y = fmaxf(v.y, 0.f);
                }
                if (EPI == 2) {
                    const float2 rr = *reinterpret_cast<const float2*>(
                        resid + (size_t)m * Ntot + n);
                    v.x += rr.x; v.y += rr.y;
                } else {
                    // output feeds another GEMM / attention: pre-round to tf32
                    v.x = tf32_rna(v.x); v.y = tf32_rna(v.y);
                }
                *reinterpret_cast<float2*>(C + (size_t)m * Ntot + n) = v;
            }
        }
    }
}

// =====================================================================
// Tensor-core flash attention (causal, tf32 mma.sync), cp.async K/V
// double buffer. BM=128 (8 warps x 16 q rows), BN=64, DH=64.
// qkv is pre-rounded tf32 (QKV-GEMM epilogue) -> raw copies, no cvt.
// =====================================================================
#define QPAD 68
#define KPAD 68
#define VPAD 72
#define ASTG_FLOATS (64 * KPAD + 64 * VPAD)   // 8960
#define ASTG_BYTES  (ASTG_FLOATS * 4)         // 35840
#define AKBYTES     (64 * KPAD * 4)           // 17408
#define ATTN_SMEM   (2 * ASTG_BYTES)          // 71680

__global__ void __launch_bounds__(256)
attn_tc(const float* __restrict__ qkv, float* __restrict__ o)
{
    extern __shared__ float sma[];
    const uint32_t sbase = smem_u32(sma);

    const int qt   = (gridDim.x - 1) - blockIdx.x;   // heavy tiles first
    const int h    = blockIdx.y;
    const int b    = blockIdx.z;
    const int tid  = threadIdx.x;
    const int lane = tid & 31;
    const int w    = tid >> 5;
    const int grp  = lane >> 2;
    const int tig  = lane & 3;

    const int q0 = qt * 128;
    const size_t base = (size_t)b * Tn * N3E + (size_t)h * DHn;

    // ---- stage Q (scaled; values tf32-exact, scale is 2^-5 => exact) ----
    #pragma unroll
    for (int p = 0; p < 8; p++) {
        const int idx = tid + p * 256;
        const int r = idx >> 4, c4 = (idx & 15) << 2;
        float4 v = *reinterpret_cast<const float4*>(
            qkv + base + (size_t)(q0 + r) * N3E + c4);
        v.x *= 0.03125f; v.y *= 0.03125f; v.z *= 0.03125f; v.w *= 0.03125f;
        *reinterpret_cast<float4*>(&sma[r * QPAD + c4]) = v;
    }
    __syncthreads();

    // ---- extract Q fragments ----
    uint32_t qa[8][4];
    {
        const float* qrow_lo = &sma[(w * 16 + grp) * QPAD];
        const float* qrow_hi = qrow_lo + 8 * QPAD;
        #pragma unroll
        for (int ks = 0; ks < 8; ks++) {
            qa[ks][0] = __float_as_uint(qrow_lo[ks * 8 + tig]);
            qa[ks][1] = __float_as_uint(qrow_hi[ks * 8 + tig]);
            qa[ks][2] = __float_as_uint(qrow_lo[ks * 8 + tig + 4]);
            qa[ks][3] = __float_as_uint(qrow_hi[ks * 8 + tig + 4]);
        }
    }
    __syncthreads();   // Q area free before cp.async overwrites it

    auto issue_kv = [&](int kt, int buf) {
        const int k0 = kt * 64;
        const uint32_t kb = sbase + (uint32_t)buf * ASTG_BYTES;
        #pragma unroll
        for (int p = 0; p < 4; p++) {
            const int idx = tid + p * 256;
            const int r = idx >> 4, c4 = (idx & 15) << 2;
            cp_async16(kb + (uint32_t)(r * KPAD + c4) * 4u,
                       qkv + base + En + (size_t)(k0 + r) * N3E + c4);
            cp_async16(kb + AKBYTES + (uint32_t)(r * VPAD + c4) * 4u,
                       qkv + base + 2 * En + (size_t)(k0 + r) * N3E + c4);
        }
        cp_commit();
    };

    float o_acc[8][4];
    #pragma unroll
    for (int nt = 0; nt < 8; nt++)
        #pragma unroll
        for (int e = 0; e < 4; e++) o_acc[nt][e] = 0.f;
    float m_lo = -1e30f, m_hi = -1e30f, l_lo = 0.f, l_hi = 0.f;

    const int nkt   = 2 * qt + 2;
    const int lr_lo = w * 16 + grp;
    const int lr_hi = lr_lo + 8;
    const int src   = (lane & ~3) | (tig >> 1);
    const int src2  = src + 2;

    issue_kv(0, 0);

    for (int kt = 0; kt < nkt; kt++) {
        const int buf = kt & 1;
        const int k0  = kt * 64;

        cp_wait<0>();       // tile kt landed (only pending group)
        __syncthreads();    // visible to all; all warps done with buf^1
        if (kt + 1 < nkt) issue_kv(kt + 1, buf ^ 1);

        const float* Ks = sma + buf * ASTG_FLOATS;
        const float* Vs = Ks + 64 * KPAD;

        const bool skip = (kt == nkt - 1) && (w < 4);
        if (!skip) {
            // ---- S = (Q*scale) @ K^T ----
            float s[8][4];
            #pragma unroll
            for (int nt = 0; nt < 8; nt++)
                #pragma unroll
                for (int e = 0; e < 4; e++) s[nt][e] = 0.f;

            #pragma unroll
            for (int nt = 0; nt < 8; nt++) {
                const float* kbase = &Ks[(nt * 8 + grp) * KPAD];
                #pragma unroll
                for (int ks = 0; ks < 8; ks++) {
                    uint32_t bfr[2];
                    bfr[0] = __float_as_uint(kbase[ks * 8 + tig]);
                    bfr[1] = __float_as_uint(kbase[ks * 8 + tig + 4]);
                    mma_tf32(s[nt], qa[ks], bfr);
                }
            }

            // ---- causal mask (only last two kv tiles can clip) ----
            if (kt >= nkt - 2) {
                const int koff = k0 - q0;
                #pragma unroll
                for (int nt = 0; nt < 8; nt++)
                    #pragma unroll
                    for (int e = 0; e < 2; e++) {
                        const int lc = koff + nt * 8 + 2 * tig + e;
                        if (lc > lr_lo) s[nt][e]     = -1e30f;
                        if (lc > lr_hi) s[nt][e + 2] = -1e30f;
                    }
            }

            // ---- online softmax ----
            float mx_lo = -1e30f, mx_hi = -1e30f;
            #pragma unroll
            for (int nt = 0; nt < 8; nt++) {
                mx_lo = fmaxf(mx_lo, fmaxf(s[nt][0], s[nt][1]));
                mx_hi = fmaxf(mx_hi, fmaxf(s[nt][2], s[nt][3]));
            }
            #pragma unroll
            for (int off = 1; off <= 2; off <<= 1) {
                mx_lo = fmaxf(mx_lo, __shfl_xor_sync(0xffffffffu, mx_lo, off));
                mx_hi = fmaxf(mx_hi, __shfl_xor_sync(0xffffffffu, mx_hi, off));
            }
            const float mn_lo = fmaxf(m_lo, mx_lo);
            const float mn_hi = fmaxf(m_hi, mx_hi);
            const float corr_lo = __expf(m_lo - mn_lo);
            const float corr_hi = __expf(m_hi - mn_hi);
            m_lo = mn_lo; m_hi = mn_hi;

            float rs_lo = 0.f, rs_hi = 0.f;
            #pragma unroll
            for (int nt = 0; nt < 8; nt++) {
                s[nt][0] = __expf(s[nt][0] - mn_lo);
                s[nt][1] = __expf(s[nt][1] - mn_lo);
                s[nt][2] = __expf(s[nt][2] - mn_hi);
                s[nt][3] = __expf(s[nt][3] - mn_hi);
                rs_lo += s[nt][0] + s[nt][1];
                rs_hi += s[nt][2] + s[nt][3];
            }
            #pragma unroll
            for (int off = 1; off <= 2; off <<= 1) {
                rs_lo += __shfl_xor_sync(0xffffffffu, rs_lo, off);
                rs_hi += __shfl_xor_sync(0xffffffffu, rs_hi, off);
            }
            l_lo = l_lo * corr_lo + rs_lo;
            l_hi = l_hi * corr_hi + rs_hi;
            #pragma unroll
            for (int nt = 0; nt < 8; nt++) {
                o_acc[nt][0] *= corr_lo; o_acc[nt][1] *= corr_lo;
                o_acc[nt][2] *= corr_hi; o_acc[nt][3] *= corr_hi;
            }

            // ---- P -> tf32 ----
            #pragma unroll
            for (int nt = 0; nt < 8; nt++)
                #pragma unroll
                for (int e = 0; e < 4; e++)
                    s[nt][e] = tf32_rna(s[nt][e]);

            // ---- O += P @ V (A frags via quad shfl) ----
            #pragma unroll
            for (int ks = 0; ks < 8; ks++) {
                const uint32_t p0 = __float_as_uint(s[ks][0]);
                const uint32_t p1 = __float_as_uint(s[ks][1]);
                const uint32_t p2 = __float_as_uint(s[ks][2]);
                const uint32_t p3 = __float_as_uint(s[ks][3]);
                const uint32_t v0 = __shfl_sync(0xffffffffu, p0, src);
                const uint32_t v1 = __shfl_sync(0xffffffffu, p1, src);
                const uint32_t v2 = __shfl_sync(0xffffffffu, p2, src);
                const uint32_t v3 = __shfl_sync(0xffffffffu, p3, src);
                const uint32_t w0 = __shfl_sync(0xffffffffu, p0, src2);
                const uint32_t w1 = __shfl_sync(0xffffffffu, p1, src2);
                const uint32_t w2 = __shfl_sync(0xffffffffu, p2, src2);
                const uint32_t w3 = __shfl_sync(0xffffffffu, p3, src2);
                uint32_t a[4];
                a[0] = (tig & 1) ? v1 : v0;
                a[1] = (tig & 1) ? v3 : v2;
                a[2] = (tig & 1) ? w1 : w0;
                a[3] = (tig & 1) ? w3 : w2;

                const float* vb0 = &Vs[(ks * 8 + tig) * VPAD];
                const float* vb1 = &Vs[(ks * 8 + tig + 4) * VPAD];
                #pragma unroll
                for (int nt = 0; nt < 8; nt++) {
                    uint32_t bfr[2];
                    bfr[0] = __float_as_uint(vb0[nt * 8 + grp]);
                    bfr[1] = __float_as_uint(vb1[nt * 8 + grp]);
                    mma_tf32(o_acc[nt], a, bfr);
                }
            }
        }
    }

    // ---- normalize & write (round: o feeds the Wo GEMM) ----
    const float inv_lo = 1.0f / l_lo;
    const float inv_hi = 1.0f / l_hi;
    const size_t obase = (size_t)b * Tn * En + (size_t)h * DHn;
    const int r_lo = q0 + w * 16 + grp;
    #pragma unroll
    for (int nt = 0; nt < 8; nt++) {
        const int c = nt * 8 + 2 * tig;
        float2 vlo, vhi;
        vlo.x = tf32_rna(o_acc[nt][0] * inv_lo);
        vlo.y = tf32_rna(o_acc[nt][1] * inv_lo);
        vhi.x = tf32_rna(o_acc[nt][2] * inv_hi);
        vhi.y = tf32_rna(o_acc[nt][3] * inv_hi);
        *reinterpret_cast<float2*>(o + obase + (size_t)r_lo * En + c)       = vlo;
        *reinterpret_cast<float2*>(o + obase + (size_t)(r_lo + 8) * En + c) = vhi;
    }
}

// =====================================================================
// launch
// =====================================================================
extern "C" void kernel_launch(void* const* d_in, const int* in_sizes, int n_in,
                              void* d_out, int out_size)
{
    const float* x   = (const float*)d_in[0];
    const float* Wq  = (const float*)d_in[1];
    const float* Wk  = (const float*)d_in[2];
    const float* Wv  = (const float*)d_in[3];
    const float* Wo  = (const float*)d_in[4];
    const float* bo  = (const float*)d_in[5];
    const float* W1  = (const float*)d_in[6];
    const float* b1  = (const float*)d_in[7];
    const float* W2  = (const float*)d_in[8];
    const float* b2  = (const float*)d_in[9];
    const float* g1  = (const float*)d_in[10];
    const float* be1 = (const float*)d_in[11];
    const float* g2  = (const float*)d_in[12];
    const float* be2 = (const float*)d_in[13];
    float* out = (float*)d_out;
    (void)in_sizes; (void)n_in; (void)out_size;

    float *h, *qkv, *o, *x2, *h2, *ff, *wqkvt, *wot, *w1t, *w2t;
    cudaGetSymbolAddress((void**)&h,     g_h);
    cudaGetSymbolAddress((void**)&qkv,   g_qkv);
    cudaGetSymbolAddress((void**)&o,     g_o);
    cudaGetSymbolAddress((void**)&x2,    g_x2);
    cudaGetSymbolAddress((void**)&h2,    g_h2);
    cudaGetSymbolAddress((void**)&ff,    g_ff);
    cudaGetSymbolAddress((void**)&wqkvt, g_wqkvt);
    cudaGetSymbolAddress((void**)&wot,   g_wot);
    cudaGetSymbolAddress((void**)&w1t,   g_w1t);
    cudaGetSymbolAddress((void**)&w2t,   g_w2t);

    cudaFuncSetAttribute(attn_tc,
                         cudaFuncAttributeMaxDynamicSharedMemorySize, ATTN_SMEM);
    cudaFuncSetAttribute(gemm_mma<0>,
                         cudaFuncAttributeMaxDynamicSharedMemorySize, GEMM_SMEM);
    cudaFuncSetAttribute(gemm_mma<1>,
                         cudaFuncAttributeMaxDynamicSharedMemorySize, GEMM_SMEM);
    cudaFuncSetAttribute(gemm_mma<2>,
                         cudaFuncAttributeMaxDynamicSharedMemorySize, GEMM_SMEM);

    const dim3 tb(32, 8);
    // weights -> K-major, tf32-rounded
    transpose_sq4<<<dim3(En / 32, En / 32, 4), tb>>>(
        Wq, Wk, Wv, Wo,
        wqkvt, wqkvt + En * En, wqkvt + 2 * En * En, wot);
    transpose_kernel<<<dim3(DFFn / 32, En / 32), tb>>>(W1, w1t, En,   DFFn);
    transpose_kernel<<<dim3(En / 32, DFFn / 32), tb>>>(W2, w2t, DFFn, En);

    // 1. ln1 (tf32-rounded out)
    ln_kernel<<<MTn, 256>>>(x, g1, be1, h);
    // 2. fused QKV GEMM (rounded out)
    gemm_mma<0><<<dim3(N3E / 128, MTn / 128), 256, GEMM_SMEM>>>(
        h, wqkvt, qkv, En, N3E, nullptr, nullptr);
    // 3. attention (tensor core, async K/V; rounded out)
    attn_tc<<<dim3(Tn / 128, Hn, Bn), 256, ATTN_SMEM>>>(qkv, o);
    // 4. out proj + bias + residual -> x2 (raw fp32)
    gemm_mma<2><<<dim3(En / 128, MTn / 128), 256, GEMM_SMEM>>>(
        o, wot, x2, En, En, bo, x);
    // 5. ln2 (rounded out)
    ln_kernel<<<MTn, 256>>>(x2, g2, be2, h2);
    // 6. FFN1 (+bias, ReLU; rounded out)
    gemm_mma<1><<<dim3(DFFn / 128, MTn / 128), 256, GEMM_SMEM>>>(
        h2, w1t, ff, En, DFFn, b1, nullptr);
    // 7. FFN2 (+bias +residual) -> out (raw fp32)
    gemm_mma<2><<<dim3(En / 128, MTn / 128), 256, GEMM_SMEM>>>(
        ff, w2t, out, DFFn, En, b2, x2);
}